// round 15
// baseline (speedup 1.0000x reference)
#include <cuda_runtime.h>

typedef unsigned long long u64;
typedef unsigned int u32;

// Problem constants
#define T_  4
#define B_  8
#define C_  512
#define D_  768
#define H_  12
#define DH  64
#define BC  (B_*C_)          // 4096
#define BCD (BC*D_)          // 3145728

// Persistent scratch (allocation-free: __device__ globals)
// Spike tensors double-buffered (buf = t&1) to decouple qkv(t+2) from attn(t).
__device__ float  g_mem[5][BCD];
__device__ float  g_spk2[2][BCD];     // sv
__device__ float  g_spk3[2][BCD];     // satt
__device__ float  g_x2[BCD];          // projection output (pre-BN)
__device__ u64    g_qb[2][BC * H_];
__device__ u64    g_kb[2][BC * H_];
__device__ float  g_cq[T_ * BCD];
__device__ float  g_ck[T_ * BCD];
__device__ float  g_cv[T_ * BCD];
__device__ float  g_wc[4][D_ * D_];
__device__ double g_bnsum[32 * D_];
__device__ double g_bnsq[32 * D_];
__device__ float  g_mean[D_];
__device__ float  g_rstd[D_];

// ---------------------------------------------------------------------------
__device__ __forceinline__ float tf32r(float x) {
    unsigned u;
    asm("cvt.rna.tf32.f32 %0, %1;" : "=r"(u) : "f"(x));
    return __uint_as_float(u);
}
__device__ __forceinline__ u32 smem_u32(const void* p) {
    u32 a;
    asm("{ .reg .u64 t; cvta.to.shared.u64 t, %1; cvt.u32.u64 %0, t; }" : "=r"(a) : "l"(p));
    return a;
}
#define CP_ASYNC16(saddr, gptr) \
    asm volatile("cp.async.ca.shared.global [%0], [%1], 16;" :: "r"(saddr), "l"(gptr))
#define CP_COMMIT() asm volatile("cp.async.commit_group;" ::: "memory")
#define CP_WAIT(n)  asm volatile("cp.async.wait_group %0;" :: "n"(n) : "memory")

__device__ __forceinline__ void mma_tf32(float* d, const u32* a, const u32* b) {
    asm volatile(
        "mma.sync.aligned.m16n8k8.row.col.f32.tf32.tf32.f32 "
        "{%0,%1,%2,%3}, {%4,%5,%6,%7}, {%8,%9}, {%0,%1,%2,%3};"
        : "+f"(d[0]), "+f"(d[1]), "+f"(d[2]), "+f"(d[3])
        : "r"(a[0]), "r"(a[1]), "r"(a[2]), "r"(a[3]), "r"(b[0]), "r"(b[1]));
}
__device__ __forceinline__ void ldsm_x4(u32* r, u32 saddr) {
    asm volatile("ldmatrix.sync.aligned.m8n8.x4.shared.b16 {%0,%1,%2,%3}, [%4];"
                 : "=r"(r[0]), "=r"(r[1]), "=r"(r[2]), "=r"(r[3]) : "r"(saddr));
}

// ---------------------------------------------------------------------------
__global__ void vout_copy_kernel(const float* __restrict__ v, float* __restrict__ o) {
    const size_t n4 = (size_t)T_ * BCD / 4;
    size_t i = (size_t)blockIdx.x * blockDim.x + threadIdx.x;
    if (i < n4) {
        float4 val = ((const float4*)v)[i];
        float4* o4 = (float4*)o;
        o4[i]          = val;
        o4[i + n4]     = val;
        o4[i + 2 * n4] = val;
        o4[i + 3 * n4] = val;
    }
}

#define N4_IN  (T_ * BCD / 4)
#define N4_W   (D_ * D_ / 4)
__global__ void cvt_all_kernel(const float4* __restrict__ q, const float4* __restrict__ k,
                               const float4* __restrict__ v, const float4* __restrict__ qw,
                               const float4* __restrict__ kw, const float4* __restrict__ vw,
                               const float4* __restrict__ pw) {
    size_t i = (size_t)blockIdx.x * blockDim.x + threadIdx.x;
    const float4* src;
    float4* dst;
    if (i < 3 * (size_t)N4_IN) {
        int which = (int)(i / N4_IN);
        size_t off = i - (size_t)which * N4_IN;
        src = (which == 0 ? q : (which == 1 ? k : v)) + off;
        dst = (float4*)(which == 0 ? g_cq : (which == 1 ? g_ck : g_cv)) + off;
    } else {
        size_t j = i - 3 * (size_t)N4_IN;
        if (j >= 4 * (size_t)N4_W) return;
        int which = (int)(j / N4_W);
        size_t off = j - (size_t)which * N4_W;
        src = (which == 0 ? qw : (which == 1 ? kw : (which == 2 ? vw : pw))) + off;
        dst = (float4*)&g_wc[which][0] + off;
    }
    float4 x = *src;
    *dst = make_float4(tf32r(x.x), tf32r(x.y), tf32r(x.z), tf32r(x.w));
}

// ---------------------------------------------------------------------------
// Dense TF32 GEMM: CTA tile 128(m)x64(n), BK=32, THREE-stage cp.async with
// XOR-swizzled pad-free smem (24KB/stage), ONE barrier per chunk.
// Schedule: wait(1) -> barrier -> issue(c+2) -> compute(c).
//   - barrier after wait gives cross-thread cp.async visibility (R13 lesson)
//   - barrier also proves compute(c-1) done by ALL threads, so overwriting
//     buffer (c+2)%3 == (c-1)%3 is safe.
// Swizzle: 128B rows; 16B-granule column col16' = col16 ^ (row & 7).
// Fragment rows always satisfy row&7 == lane's li -> conflict-free ldmatrix.
#define STAGE3_BYTES 24576      // A 128x128B + B 64x128B
#define DSM_BYTES   (3 * STAGE3_BYTES)

__global__ __launch_bounds__(256, 3) void dense_mma_gemm(
    const float* __restrict__ Xq, const float* __restrict__ Xk, const float* __restrict__ Xv,
    const float* __restrict__ Wq, const float* __restrict__ Wk, const float* __restrict__ Wv,
    const float* __restrict__ bq, const float* __restrict__ bk, const float* __restrict__ bv,
    int mode, int first, int buf)
{
    extern __shared__ char dsm[];
    const u32 sb = smem_u32(dsm);

    const int z = blockIdx.z;
    const float* X;
    const float* W;
    const float* bias;
    float* mem = nullptr;
    float* spk = nullptr;
    float* out = nullptr;
    u32*   bitout = nullptr;
    if (mode) {
        X    = (z == 0) ? Xq : ((z == 1) ? Xk : Xv);
        W    = (z == 0) ? Wq : ((z == 1) ? Wk : Wv);
        bias = (z == 0) ? bq : ((z == 1) ? bk : bv);
        mem  = g_mem[z];
        if (z == 2) spk = g_spk2[buf];
        else bitout = (z == 0) ? (u32*)g_qb[buf] : (u32*)g_kb[buf];
    } else {
        X = g_spk3[buf]; W = Wq; bias = bq; out = g_x2;
    }

    const int tid  = threadIdx.x;
    const int wid  = tid >> 5, lane = tid & 31;
    const int g    = lane >> 2, c = lane & 3;
    const int wm   = wid & 3;
    const int wn   = wid >> 2;
    const int m0   = blockIdx.y * 128;
    const int n0   = blockIdx.x * 64;

    float acc[2][4][4];
#pragma unroll
    for (int im = 0; im < 2; im++)
#pragma unroll
        for (int in = 0; in < 4; in++)
#pragma unroll
            for (int r = 0; r < 4; r++) acc[im][in][r] = 0.0f;

    // Loader mapping: row = tid>>3 (0..31, +pass*32), seg = tid&7 (16B granule)
    const int row = tid >> 3, seg = tid & 7;
    const u32 swoff = (u32)((seg ^ (row & 7)) << 4);   // row&7 pass-invariant

    auto issue_stage = [&](int bufs, int chunk) {
        const int k0 = chunk * 32;
        const u32 sA = sb + bufs * STAGE3_BYTES;
        const u32 sB = sA + 16384;
#pragma unroll
        for (int pass = 0; pass < 4; pass++) {
            int rr = row + pass * 32;
            CP_ASYNC16(sA + (u32)(rr * 128) + swoff,
                       &X[(size_t)(m0 + rr) * 768 + k0 + seg * 4]);
        }
#pragma unroll
        for (int pass = 0; pass < 2; pass++) {
            int rr = row + pass * 32;
            CP_ASYNC16(sB + (u32)(rr * 128) + swoff,
                       &W[(size_t)(n0 + rr) * 768 + k0 + seg * 4]);
        }
    };

    // ldmatrix fragment addressing (swizzled)
    const int li = lane & 7, bi = lane >> 3;
    const u32 aRowOff = (u32)((wm * 32 + li + ((bi & 1) << 3)) * 128);
    const int aColSel = bi >> 1;
    const u32 bRowOff = (u32)(16384 + (wn * 32 + ((bi >> 1) << 3) + li) * 128);
    const int bColSel = bi & 1;

    issue_stage(0, 0); CP_COMMIT();
    issue_stage(1, 1); CP_COMMIT();

    for (int chunk = 0; chunk < 24; chunk++) {
        if (chunk < 23) { CP_WAIT(1); } else { CP_WAIT(0); }
        __syncthreads();   // visibility of stage `chunk` + all readers of (chunk-1) done
        if (chunk + 2 < 24) {
            issue_stage((chunk + 2) % 3, chunk + 2);
            CP_COMMIT();
        }

        const u32 stBase = sb + (u32)((chunk % 3) * STAGE3_BYTES);
#pragma unroll
        for (int ka = 0; ka < 4; ka++) {
            const u32 aCol = (u32)(((ka * 2 + aColSel) ^ li) << 4);
            const u32 bCol = (u32)(((ka * 2 + bColSel) ^ li) << 4);
            u32 a[2][4], b[4][2];
#pragma unroll
            for (int im = 0; im < 2; im++)
                ldsm_x4(a[im], stBase + aRowOff + (u32)(im * 2048) + aCol);
#pragma unroll
            for (int ip = 0; ip < 2; ip++) {
                u32 t4[4];
                ldsm_x4(t4, stBase + bRowOff + (u32)(ip * 2048) + bCol);
                b[2 * ip][0]     = t4[0];
                b[2 * ip][1]     = t4[1];
                b[2 * ip + 1][0] = t4[2];
                b[2 * ip + 1][1] = t4[3];
            }
#pragma unroll
            for (int im = 0; im < 2; im++)
#pragma unroll
                for (int in = 0; in < 4; in++)
                    mma_tf32(acc[im][in], a[im], b[in]);
        }
    }

    // Epilogue
    float* sE = (float*)dsm;                          // 128*66*4 = 33792 B
    double* dredS = (double*)(dsm + 33792);
    double* dredQ = (double*)(dsm + 33792 + 4096);
    __syncthreads();
#pragma unroll
    for (int im = 0; im < 2; im++)
#pragma unroll
        for (int in = 0; in < 4; in++) {
            int rr   = wm * 32 + im * 16 + g;
            int colb = wn * 32 + in * 8 + 2 * c;
            sE[rr * 66 + colb]           = acc[im][in][0];
            sE[rr * 66 + colb + 1]       = acc[im][in][1];
            sE[(rr + 8) * 66 + colb]     = acc[im][in][2];
            sE[(rr + 8) * 66 + colb + 1] = acc[im][in][3];
        }
    __syncthreads();

    const int head = n0 >> 6;
#pragma unroll
    for (int nc = 0; nc < 2; nc++) {
        const int nn = n0 + nc * 32 + lane;
        const float bvv = bias[nn];
        double ds = 0.0, dss = 0.0;
        for (int rr = wid * 16; rr < wid * 16 + 16; rr++) {
            float y = sE[rr * 66 + nc * 32 + lane] + bvv;
            int m = m0 + rr;
            size_t idx = (size_t)m * 768 + nn;
            if (mode) {
                float mp    = first ? 0.0f : mem[idx];
                float reset = (mp > 1.0f) ? 1.0f : 0.0f;
                float mn    = 0.6f * mp + y - reset;
                mem[idx] = mn;
                float sp = (mn > 1.0f) ? 1.0f : 0.0f;
                if (z == 2) {
                    spk[idx] = sp;
                } else {
                    u32 bits = __ballot_sync(0xffffffffu, sp > 0.5f);
                    if (lane == 0) bitout[(m * H_ + head) * 2 + nc] = bits;
                }
            } else {
                out[idx] = y;
                ds  += (double)y;
                dss += (double)y * (double)y;
            }
        }
        if (mode == 0) {
            dredS[wid * 64 + nc * 32 + lane] = ds;
            dredQ[wid * 64 + nc * 32 + lane] = dss;
        }
    }

    if (mode == 0) {
        __syncthreads();
        if (tid < 64) {
            double s = 0.0, qq = 0.0;
#pragma unroll
            for (int w = 0; w < 8; w++) {
                s  += dredS[w * 64 + tid];
                qq += dredQ[w * 64 + tid];
            }
            g_bnsum[blockIdx.y * 768 + n0 + tid] = s;
            g_bnsq[blockIdx.y * 768 + n0 + tid]  = qq;
        }
    }
}

// ---------------------------------------------------------------------------
// Fused attention: inline popcount S-frags + HMMA PV + LIF.
// Vs double-buffered -> ONE barrier per jt iteration (proven R14).
__global__ __launch_bounds__(256) void attn_mma_kernel(int first, int buf) {
    __shared__ u64   Kb[512];
    __shared__ float Vs[2][64 * 36];

    const int bh = blockIdx.y;
    const int b  = bh / H_;
    const int h  = bh - b * H_;
    const int i0 = blockIdx.x * 128;
    const int tid = threadIdx.x;
    const int wid = tid >> 5, lane = tid & 31;
    const int g = lane >> 2, cc = lane & 3;

    const u64* qbp = g_qb[buf];
    const u64* kbp = g_kb[buf];
    Kb[tid]       = kbp[(size_t)(b * C_ + tid) * H_ + h];
    Kb[tid + 256] = kbp[(size_t)(b * C_ + tid + 256) * H_ + h];

    const int irow0 = i0 + wid * 16 + g;
    const u64 q0 = qbp[(size_t)(b * C_ + irow0) * H_ + h];
    const u64 q1 = qbp[(size_t)(b * C_ + irow0 + 8) * H_ + h];

    const float* V = g_spk2[buf] + (size_t)b * C_ * D_ + h * DH;

    float acc[8][4];
#pragma unroll
    for (int in = 0; in < 8; in++)
#pragma unroll
        for (int r = 0; r < 4; r++) acc[in][r] = 0.0f;

    const int vj = tid >> 3, vd = tid & 7;
    float4 va = *(const float4*)&V[(size_t)vj * 768 + vd * 4];
    float4 vb = *(const float4*)&V[(size_t)vj * 768 + 32 + vd * 4];

    for (int c = 0; c < 16; c++) {
        float* Vw = Vs[c & 1];
        Vw[(4 * vd + 0) * 36 + vj] = va.x;
        Vw[(4 * vd + 1) * 36 + vj] = va.y;
        Vw[(4 * vd + 2) * 36 + vj] = va.z;
        Vw[(4 * vd + 3) * 36 + vj] = va.w;
        Vw[(32 + 4 * vd + 0) * 36 + vj] = vb.x;
        Vw[(32 + 4 * vd + 1) * 36 + vj] = vb.y;
        Vw[(32 + 4 * vd + 2) * 36 + vj] = vb.z;
        Vw[(32 + 4 * vd + 3) * 36 + vj] = vb.w;
        __syncthreads();   // Vw stored (and Kb on c==0); prev-buffer readers done
        if (c < 15) {
            va = *(const float4*)&V[(size_t)((c + 1) * 32 + vj) * 768 + vd * 4];
            vb = *(const float4*)&V[(size_t)((c + 1) * 32 + vj) * 768 + 32 + vd * 4];
        }

        const u32* Vsu = (const u32*)Vs[c & 1];
#pragma unroll
        for (int ka = 0; ka < 4; ka++) {
            const int jb = c * 32 + ka * 8;
            const u64 kb0 = Kb[jb + cc];
            const u64 kb4 = Kb[jb + cc + 4];
            u32 a[4];
            a[0] = __float_as_uint(tf32r(0.18f * (float)__popcll(q0 & kb0)));
            a[1] = __float_as_uint(tf32r(0.18f * (float)__popcll(q1 & kb0)));
            a[2] = __float_as_uint(tf32r(0.18f * (float)__popcll(q0 & kb4)));
            a[3] = __float_as_uint(tf32r(0.18f * (float)__popcll(q1 & kb4)));
#pragma unroll
            for (int in = 0; in < 8; in++) {
                u32 bfr[2];
                bfr[0] = Vsu[(in * 8 + g) * 36 + ka * 8 + cc];
                bfr[1] = Vsu[(in * 8 + g) * 36 + ka * 8 + cc + 4];
                mma_tf32(acc[in], a, bfr);
            }
        }
    }

    float* mem = g_mem[3];
    float* spk = g_spk3[buf];
#pragma unroll
    for (int in = 0; in < 8; in++) {
        int col = h * DH + in * 8 + 2 * cc;
        size_t idx0 = (size_t)(b * C_ + irow0) * 768 + col;
        size_t idx1 = (size_t)(b * C_ + irow0 + 8) * 768 + col;
#pragma unroll
        for (int e = 0; e < 2; e++) {
            float mp    = first ? 0.0f : mem[idx0 + e];
            float reset = (mp > 1.0f) ? 1.0f : 0.0f;
            float mn    = 0.6f * mp + acc[in][e] - reset;
            mem[idx0 + e] = mn;
            spk[idx0 + e] = (mn > 1.0f) ? 1.0f : 0.0f;
            float mp1    = first ? 0.0f : mem[idx1 + e];
            float reset1 = (mp1 > 1.0f) ? 1.0f : 0.0f;
            float mn1    = 0.6f * mp1 + acc[in][2 + e] - reset1;
            mem[idx1 + e] = mn1;
            spk[idx1 + e] = (mn1 > 1.0f) ? 1.0f : 0.0f;
        }
    }
}

// ---------------------------------------------------------------------------
__global__ void bn_finalize_kernel() {
    int ch = blockIdx.x * blockDim.x + threadIdx.x;
    if (ch < 768) {
        double s = 0.0, q = 0.0;
#pragma unroll
        for (int p = 0; p < 32; p++) {
            s += g_bnsum[p * 768 + ch];
            q += g_bnsq[p * 768 + ch];
        }
        double mean = s * (1.0 / 4096.0);
        double var  = q * (1.0 / 4096.0) - mean * mean;
        g_mean[ch] = (float)mean;
        g_rstd[ch] = rsqrtf((float)var + 1e-5f);
    }
}

__global__ void bn_apply_lif_kernel(const float* __restrict__ bnw,
                                    const float* __restrict__ bnb,
                                    float* __restrict__ outp, int first) {
    size_t i4 = (size_t)blockIdx.x * blockDim.x + threadIdx.x;
    size_t base = i4 * 4;
    int ch = (int)(base % 768);
    float4 x  = ((const float4*)g_x2)[i4];
    float4 mp = first ? make_float4(0.f, 0.f, 0.f, 0.f) : ((const float4*)g_mem[4])[i4];
    float xs[4] = {x.x, x.y, x.z, x.w};
    float ms[4] = {mp.x, mp.y, mp.z, mp.w};
    float4 mo, oo;
    float* mop = (float*)&mo;
    float* oop = (float*)&oo;
#pragma unroll
    for (int j = 0; j < 4; j++) {
        int cj = ch + j;
        float cur = (xs[j] - g_mean[cj]) * g_rstd[cj] * bnw[cj] + bnb[cj];
        float reset = (ms[j] > 1.0f) ? 1.0f : 0.0f;
        float mn    = 0.6f * ms[j] + cur - reset;
        mop[j] = mn;
        oop[j] = (mn > 1.0f) ? 1.0f : 0.0f;
    }
    ((float4*)g_mem[4])[i4] = mo;
    ((float4*)outp)[i4] = oo;
}

// ---------------------------------------------------------------------------
extern "C" void kernel_launch(void* const* d_in, const int* in_sizes, int n_in,
                              void* d_out, int out_size) {
    (void)in_sizes; (void)n_in; (void)out_size;
    const float* q   = (const float*)d_in[0];
    const float* k   = (const float*)d_in[1];
    const float* v   = (const float*)d_in[2];
    const float* qb  = (const float*)d_in[4];
    const float* kb  = (const float*)d_in[6];
    const float* vb  = (const float*)d_in[8];
    const float* pb  = (const float*)d_in[10];
    const float* bnw = (const float*)d_in[11];
    const float* bnb = (const float*)d_in[12];
    float* out = (float*)d_out;

    // One-time sync-primitive setup (first call is the eager correctness run,
    // outside graph capture). Initialization only; identical work every call.
    static cudaStream_t s2;
    static cudaEvent_t  evCvt, evQ[4], evA[2];
    static bool inited = false;
    if (!inited) {
        cudaStreamCreateWithFlags(&s2, cudaStreamNonBlocking);
        cudaEventCreateWithFlags(&evCvt, cudaEventDisableTiming);
        for (int i = 0; i < 4; i++) cudaEventCreateWithFlags(&evQ[i], cudaEventDisableTiming);
        for (int i = 0; i < 2; i++) cudaEventCreateWithFlags(&evA[i], cudaEventDisableTiming);
        cudaFuncSetAttribute(dense_mma_gemm, cudaFuncAttributeMaxDynamicSharedMemorySize,
                             DSM_BYTES);
        inited = true;
    }

    float* cq; cudaGetSymbolAddress((void**)&cq, g_cq);
    float* ck; cudaGetSymbolAddress((void**)&ck, g_ck);
    float* cv; cudaGetSymbolAddress((void**)&cv, g_cv);
    float* wc; cudaGetSymbolAddress((void**)&wc, g_wc);

    // Preamble (main stream)
    vout_copy_kernel<<<12288, 256>>>(v, out + (size_t)T_ * BCD);
    const int totalCvt = 3 * N4_IN + 4 * N4_W;
    cvt_all_kernel<<<(totalCvt + 255) / 256, 256>>>(
        (const float4*)q, (const float4*)k, (const float4*)v,
        (const float4*)d_in[3], (const float4*)d_in[5],
        (const float4*)d_in[7], (const float4*)d_in[9]);
    cudaEventRecord(evCvt, 0);

    auto launch_qkv = [&](int t) {
        const float* qt = cq + (size_t)t * BCD;
        const float* kt = ck + (size_t)t * BCD;
        const float* vt = cv + (size_t)t * BCD;
        dense_mma_gemm<<<dim3(12, 32, 3), 256, DSM_BYTES, s2>>>(
            qt, kt, vt, wc + 0 * D_ * D_, wc + 1 * D_ * D_, wc + 2 * D_ * D_,
            qb, kb, vb, 1, (t == 0) ? 1 : 0, t & 1);
        cudaEventRecord(evQ[t], s2);
    };

    cudaStreamWaitEvent(s2, evCvt, 0);
    launch_qkv(0);
    launch_qkv(1);

    for (int t = 0; t < T_; t++) {
        const int first = (t == 0) ? 1 : 0;
        const int bf = t & 1;

        cudaStreamWaitEvent(0, evQ[t], 0);
        attn_mma_kernel<<<dim3(4, 96), 256>>>(first, bf);
        if (t < 2) {
            cudaEventRecord(evA[t], 0);
            cudaStreamWaitEvent(s2, evA[t], 0);
            launch_qkv(t + 2);
        }
        dense_mma_gemm<<<dim3(12, 32, 1), 256, DSM_BYTES>>>(
            nullptr, nullptr, nullptr, wc + 3 * D_ * D_, nullptr, nullptr,
            pb, nullptr, nullptr, 0, 0, bf);
        bn_finalize_kernel<<<3, 256>>>();
        bn_apply_lif_kernel<<<3072, 256>>>(bnw, bnb, out + (size_t)t * BCD, first);
    }
}

// round 16
// speedup vs baseline: 1.3302x; 1.3302x over previous
#include <cuda_runtime.h>

typedef unsigned long long u64;
typedef unsigned int u32;

// Problem constants
#define T_  4
#define B_  8
#define C_  512
#define D_  768
#define H_  12
#define DH  64
#define BC  (B_*C_)          // 4096
#define BCD (BC*D_)          // 3145728

// Persistent scratch (allocation-free: __device__ globals)
// Spike tensors double-buffered (buf = t&1) to decouple qkv(t+2) from attn(t)
// and attn(t+2) from proj(t).
__device__ float  g_mem[5][BCD];
__device__ float  g_spk2[2][BCD];     // sv
__device__ float  g_spk3[2][BCD];     // satt
__device__ float  g_x2[BCD];          // projection output (pre-BN)
__device__ u64    g_qb[2][BC * H_];
__device__ u64    g_kb[2][BC * H_];
__device__ float  g_cq[T_ * BCD];
__device__ float  g_ck[T_ * BCD];
__device__ float  g_cv[T_ * BCD];
__device__ float  g_wc[4][D_ * D_];
__device__ double g_bnsum[32 * D_];
__device__ double g_bnsq[32 * D_];
__device__ float  g_mean[D_];
__device__ float  g_rstd[D_];

// ---------------------------------------------------------------------------
__device__ __forceinline__ float tf32r(float x) {
    unsigned u;
    asm("cvt.rna.tf32.f32 %0, %1;" : "=r"(u) : "f"(x));
    return __uint_as_float(u);
}
__device__ __forceinline__ u32 smem_u32(const void* p) {
    u32 a;
    asm("{ .reg .u64 t; cvta.to.shared.u64 t, %1; cvt.u32.u64 %0, t; }" : "=r"(a) : "l"(p));
    return a;
}
#define CP_ASYNC16(saddr, gptr) \
    asm volatile("cp.async.ca.shared.global [%0], [%1], 16;" :: "r"(saddr), "l"(gptr))
#define CP_COMMIT() asm volatile("cp.async.commit_group;" ::: "memory")
#define CP_WAIT(n)  asm volatile("cp.async.wait_group %0;" :: "n"(n) : "memory")

__device__ __forceinline__ void mma_tf32(float* d, const u32* a, const u32* b) {
    asm volatile(
        "mma.sync.aligned.m16n8k8.row.col.f32.tf32.tf32.f32 "
        "{%0,%1,%2,%3}, {%4,%5,%6,%7}, {%8,%9}, {%0,%1,%2,%3};"
        : "+f"(d[0]), "+f"(d[1]), "+f"(d[2]), "+f"(d[3])
        : "r"(a[0]), "r"(a[1]), "r"(a[2]), "r"(a[3]), "r"(b[0]), "r"(b[1]));
}
__device__ __forceinline__ void ldsm_x4(u32* r, u32 saddr) {
    asm volatile("ldmatrix.sync.aligned.m8n8.x4.shared.b16 {%0,%1,%2,%3}, [%4];"
                 : "=r"(r[0]), "=r"(r[1]), "=r"(r[2]), "=r"(r[3]) : "r"(saddr));
}

// ---------------------------------------------------------------------------
__global__ void vout_copy_kernel(const float* __restrict__ v, float* __restrict__ o) {
    const size_t n4 = (size_t)T_ * BCD / 4;
    size_t i = (size_t)blockIdx.x * blockDim.x + threadIdx.x;
    if (i < n4) {
        float4 val = ((const float4*)v)[i];
        float4* o4 = (float4*)o;
        o4[i]          = val;
        o4[i + n4]     = val;
        o4[i + 2 * n4] = val;
        o4[i + 3 * n4] = val;
    }
}

#define N4_IN  (T_ * BCD / 4)
#define N4_W   (D_ * D_ / 4)
__global__ void cvt_all_kernel(const float4* __restrict__ q, const float4* __restrict__ k,
                               const float4* __restrict__ v, const float4* __restrict__ qw,
                               const float4* __restrict__ kw, const float4* __restrict__ vw,
                               const float4* __restrict__ pw) {
    size_t i = (size_t)blockIdx.x * blockDim.x + threadIdx.x;
    const float4* src;
    float4* dst;
    if (i < 3 * (size_t)N4_IN) {
        int which = (int)(i / N4_IN);
        size_t off = i - (size_t)which * N4_IN;
        src = (which == 0 ? q : (which == 1 ? k : v)) + off;
        dst = (float4*)(which == 0 ? g_cq : (which == 1 ? g_ck : g_cv)) + off;
    } else {
        size_t j = i - 3 * (size_t)N4_IN;
        if (j >= 4 * (size_t)N4_W) return;
        int which = (int)(j / N4_W);
        size_t off = j - (size_t)which * N4_W;
        src = (which == 0 ? qw : (which == 1 ? kw : (which == 2 ? vw : pw))) + off;
        dst = (float4*)&g_wc[which][0] + off;
    }
    float4 x = *src;
    *dst = make_float4(tf32r(x.x), tf32r(x.y), tf32r(x.z), tf32r(x.w));
}

// ---------------------------------------------------------------------------
// Dense TF32 GEMM: CTA tile 128(m)x64(n), BK=32, 2-stage cp.async, 3 CTAs/SM.
// R14-proven config (two barriers/chunk; padded stride-36 smem). Do not touch:
// R10 (occ=4 spill), R13 (1-barrier race), R15 (3-stage swizzle) all regressed.
#define STAGE_BYTES 27648
#define DSM_BYTES   (2 * STAGE_BYTES)

__global__ __launch_bounds__(256, 3) void dense_mma_gemm(
    const float* __restrict__ Xq, const float* __restrict__ Xk, const float* __restrict__ Xv,
    const float* __restrict__ Wq, const float* __restrict__ Wk, const float* __restrict__ Wv,
    const float* __restrict__ bq, const float* __restrict__ bk, const float* __restrict__ bv,
    int mode, int first, int buf)
{
    extern __shared__ char dsm[];
    const u32 sb = smem_u32(dsm);

    const int z = blockIdx.z;
    const float* X;
    const float* W;
    const float* bias;
    float* mem = nullptr;
    float* spk = nullptr;
    float* out = nullptr;
    u32*   bitout = nullptr;
    if (mode) {
        X    = (z == 0) ? Xq : ((z == 1) ? Xk : Xv);
        W    = (z == 0) ? Wq : ((z == 1) ? Wk : Wv);
        bias = (z == 0) ? bq : ((z == 1) ? bk : bv);
        mem  = g_mem[z];
        if (z == 2) spk = g_spk2[buf];
        else bitout = (z == 0) ? (u32*)g_qb[buf] : (u32*)g_kb[buf];
    } else {
        X = g_spk3[buf]; W = Wq; bias = bq; out = g_x2;
    }

    const int tid  = threadIdx.x;
    const int wid  = tid >> 5, lane = tid & 31;
    const int g    = lane >> 2, c = lane & 3;
    const int wm   = wid & 3;
    const int wn   = wid >> 2;
    const int m0   = blockIdx.y * 128;
    const int n0   = blockIdx.x * 64;

    float acc[2][4][4];
#pragma unroll
    for (int im = 0; im < 2; im++)
#pragma unroll
        for (int in = 0; in < 4; in++)
#pragma unroll
            for (int r = 0; r < 4; r++) acc[im][in][r] = 0.0f;

    const int row = tid >> 3, seg = tid & 7;

    auto issue_stage = [&](int bufs, int chunk) {
        const int k0 = chunk * 32;
        const u32 sA = sb + bufs * STAGE_BYTES;
        const u32 sB = sA + 18432;
#pragma unroll
        for (int pass = 0; pass < 4; pass++) {
            int rr = row + pass * 32;
            u32 off = (u32)((rr * 36 + seg * 4) * 4);
            CP_ASYNC16(sA + off, &X[(size_t)(m0 + rr) * 768 + k0 + seg * 4]);
        }
#pragma unroll
        for (int pass = 0; pass < 2; pass++) {
            int rr = row + pass * 32;
            u32 off = (u32)((rr * 36 + seg * 4) * 4);
            CP_ASYNC16(sB + off, &W[(size_t)(n0 + rr) * 768 + k0 + seg * 4]);
        }
    };

    const int li = lane & 7, bi = lane >> 3;
    const u32 aOff = (u32)(((wm * 32 + li + ((bi & 1) << 3)) * 36 + ((bi >> 1) << 2)) * 4);
    const u32 bOff = (u32)(18432 + ((wn * 32 + ((bi >> 1) << 3) + li) * 36 + ((bi & 1) << 2)) * 4);

    issue_stage(0, 0); CP_COMMIT();
    issue_stage(1, 1); CP_COMMIT();

    for (int chunk = 0; chunk < 24; chunk++) {
        if (chunk < 23) { CP_WAIT(1); } else { CP_WAIT(0); }
        __syncthreads();   // visibility: everyone's cp.async for this buffer done

        const u32 stBase = sb + (chunk & 1) * STAGE_BYTES;
#pragma unroll
        for (int ka = 0; ka < 4; ka++) {
            u32 a[2][4], b[4][2];
#pragma unroll
            for (int im = 0; im < 2; im++)
                ldsm_x4(a[im], stBase + aOff + (u32)((im * 16 * 36 + ka * 8) * 4));
#pragma unroll
            for (int ip = 0; ip < 2; ip++) {
                u32 t4[4];
                ldsm_x4(t4, stBase + bOff + (u32)((ip * 16 * 36 + ka * 8) * 4));
                b[2 * ip][0]     = t4[0];
                b[2 * ip][1]     = t4[1];
                b[2 * ip + 1][0] = t4[2];
                b[2 * ip + 1][1] = t4[3];
            }
#pragma unroll
            for (int im = 0; im < 2; im++)
#pragma unroll
                for (int in = 0; in < 4; in++)
                    mma_tf32(acc[im][in], a[im], b[in]);
        }
        __syncthreads();   // all warps done reading before refill overwrites
        if (chunk + 2 < 24) {
            issue_stage(chunk & 1, chunk + 2);
            CP_COMMIT();
        }
    }

    // Epilogue
    float* sE = (float*)dsm;                          // 128*66*4 = 33792 B
    double* dredS = (double*)(dsm + 33792);
    double* dredQ = (double*)(dsm + 33792 + 4096);
    __syncthreads();
#pragma unroll
    for (int im = 0; im < 2; im++)
#pragma unroll
        for (int in = 0; in < 4; in++) {
            int rr   = wm * 32 + im * 16 + g;
            int colb = wn * 32 + in * 8 + 2 * c;
            sE[rr * 66 + colb]           = acc[im][in][0];
            sE[rr * 66 + colb + 1]       = acc[im][in][1];
            sE[(rr + 8) * 66 + colb]     = acc[im][in][2];
            sE[(rr + 8) * 66 + colb + 1] = acc[im][in][3];
        }
    __syncthreads();

    const int head = n0 >> 6;
#pragma unroll
    for (int nc = 0; nc < 2; nc++) {
        const int nn = n0 + nc * 32 + lane;
        const float bvv = bias[nn];
        double ds = 0.0, dss = 0.0;
        for (int rr = wid * 16; rr < wid * 16 + 16; rr++) {
            float y = sE[rr * 66 + nc * 32 + lane] + bvv;
            int m = m0 + rr;
            size_t idx = (size_t)m * 768 + nn;
            if (mode) {
                float mp    = first ? 0.0f : mem[idx];
                float reset = (mp > 1.0f) ? 1.0f : 0.0f;
                float mn    = 0.6f * mp + y - reset;
                mem[idx] = mn;
                float sp = (mn > 1.0f) ? 1.0f : 0.0f;
                if (z == 2) {
                    spk[idx] = sp;
                } else {
                    u32 bits = __ballot_sync(0xffffffffu, sp > 0.5f);
                    if (lane == 0) bitout[(m * H_ + head) * 2 + nc] = bits;
                }
            } else {
                out[idx] = y;
                ds  += (double)y;
                dss += (double)y * (double)y;
            }
        }
        if (mode == 0) {
            dredS[wid * 64 + nc * 32 + lane] = ds;
            dredQ[wid * 64 + nc * 32 + lane] = dss;
        }
    }

    if (mode == 0) {
        __syncthreads();
        if (tid < 64) {
            double s = 0.0, qq = 0.0;
#pragma unroll
            for (int w = 0; w < 8; w++) {
                s  += dredS[w * 64 + tid];
                qq += dredQ[w * 64 + tid];
            }
            g_bnsum[blockIdx.y * 768 + n0 + tid] = s;
            g_bnsq[blockIdx.y * 768 + n0 + tid]  = qq;
        }
    }
}

// ---------------------------------------------------------------------------
// Fused attention: inline popcount S-frags + HMMA PV + LIF (R14-proven).
__global__ __launch_bounds__(256) void attn_mma_kernel(int first, int buf) {
    __shared__ u64   Kb[512];
    __shared__ float Vs[2][64 * 36];

    const int bh = blockIdx.y;
    const int b  = bh / H_;
    const int h  = bh - b * H_;
    const int i0 = blockIdx.x * 128;
    const int tid = threadIdx.x;
    const int wid = tid >> 5, lane = tid & 31;
    const int g = lane >> 2, cc = lane & 3;

    const u64* qbp = g_qb[buf];
    const u64* kbp = g_kb[buf];
    Kb[tid]       = kbp[(size_t)(b * C_ + tid) * H_ + h];
    Kb[tid + 256] = kbp[(size_t)(b * C_ + tid + 256) * H_ + h];

    const int irow0 = i0 + wid * 16 + g;
    const u64 q0 = qbp[(size_t)(b * C_ + irow0) * H_ + h];
    const u64 q1 = qbp[(size_t)(b * C_ + irow0 + 8) * H_ + h];

    const float* V = g_spk2[buf] + (size_t)b * C_ * D_ + h * DH;

    float acc[8][4];
#pragma unroll
    for (int in = 0; in < 8; in++)
#pragma unroll
        for (int r = 0; r < 4; r++) acc[in][r] = 0.0f;

    const int vj = tid >> 3, vd = tid & 7;
    float4 va = *(const float4*)&V[(size_t)vj * 768 + vd * 4];
    float4 vb = *(const float4*)&V[(size_t)vj * 768 + 32 + vd * 4];

    for (int c = 0; c < 16; c++) {
        float* Vw = Vs[c & 1];
        Vw[(4 * vd + 0) * 36 + vj] = va.x;
        Vw[(4 * vd + 1) * 36 + vj] = va.y;
        Vw[(4 * vd + 2) * 36 + vj] = va.z;
        Vw[(4 * vd + 3) * 36 + vj] = va.w;
        Vw[(32 + 4 * vd + 0) * 36 + vj] = vb.x;
        Vw[(32 + 4 * vd + 1) * 36 + vj] = vb.y;
        Vw[(32 + 4 * vd + 2) * 36 + vj] = vb.z;
        Vw[(32 + 4 * vd + 3) * 36 + vj] = vb.w;
        __syncthreads();   // Vw stored (and Kb on c==0); prev-buffer readers done
        if (c < 15) {
            va = *(const float4*)&V[(size_t)((c + 1) * 32 + vj) * 768 + vd * 4];
            vb = *(const float4*)&V[(size_t)((c + 1) * 32 + vj) * 768 + 32 + vd * 4];
        }

        const u32* Vsu = (const u32*)Vs[c & 1];
#pragma unroll
        for (int ka = 0; ka < 4; ka++) {
            const int jb = c * 32 + ka * 8;
            const u64 kb0 = Kb[jb + cc];
            const u64 kb4 = Kb[jb + cc + 4];
            u32 a[4];
            a[0] = __float_as_uint(tf32r(0.18f * (float)__popcll(q0 & kb0)));
            a[1] = __float_as_uint(tf32r(0.18f * (float)__popcll(q1 & kb0)));
            a[2] = __float_as_uint(tf32r(0.18f * (float)__popcll(q0 & kb4)));
            a[3] = __float_as_uint(tf32r(0.18f * (float)__popcll(q1 & kb4)));
#pragma unroll
            for (int in = 0; in < 8; in++) {
                u32 bfr[2];
                bfr[0] = Vsu[(in * 8 + g) * 36 + ka * 8 + cc];
                bfr[1] = Vsu[(in * 8 + g) * 36 + ka * 8 + cc + 4];
                mma_tf32(acc[in], a, bfr);
            }
        }
    }

    float* mem = g_mem[3];
    float* spk = g_spk3[buf];
#pragma unroll
    for (int in = 0; in < 8; in++) {
        int col = h * DH + in * 8 + 2 * cc;
        size_t idx0 = (size_t)(b * C_ + irow0) * 768 + col;
        size_t idx1 = (size_t)(b * C_ + irow0 + 8) * 768 + col;
#pragma unroll
        for (int e = 0; e < 2; e++) {
            float mp    = first ? 0.0f : mem[idx0 + e];
            float reset = (mp > 1.0f) ? 1.0f : 0.0f;
            float mn    = 0.6f * mp + acc[in][e] - reset;
            mem[idx0 + e] = mn;
            spk[idx0 + e] = (mn > 1.0f) ? 1.0f : 0.0f;
            float mp1    = first ? 0.0f : mem[idx1 + e];
            float reset1 = (mp1 > 1.0f) ? 1.0f : 0.0f;
            float mn1    = 0.6f * mp1 + acc[in][2 + e] - reset1;
            mem[idx1 + e] = mn1;
            spk[idx1 + e] = (mn1 > 1.0f) ? 1.0f : 0.0f;
        }
    }
}

// ---------------------------------------------------------------------------
__global__ void bn_finalize_kernel() {
    int ch = blockIdx.x * blockDim.x + threadIdx.x;
    if (ch < 768) {
        double s = 0.0, q = 0.0;
#pragma unroll
        for (int p = 0; p < 32; p++) {
            s += g_bnsum[p * 768 + ch];
            q += g_bnsq[p * 768 + ch];
        }
        double mean = s * (1.0 / 4096.0);
        double var  = q * (1.0 / 4096.0) - mean * mean;
        g_mean[ch] = (float)mean;
        g_rstd[ch] = rsqrtf((float)var + 1e-5f);
    }
}

__global__ void bn_apply_lif_kernel(const float* __restrict__ bnw,
                                    const float* __restrict__ bnb,
                                    float* __restrict__ outp, int first) {
    size_t i4 = (size_t)blockIdx.x * blockDim.x + threadIdx.x;
    size_t base = i4 * 4;
    int ch = (int)(base % 768);
    float4 x  = ((const float4*)g_x2)[i4];
    float4 mp = first ? make_float4(0.f, 0.f, 0.f, 0.f) : ((const float4*)g_mem[4])[i4];
    float xs[4] = {x.x, x.y, x.z, x.w};
    float ms[4] = {mp.x, mp.y, mp.z, mp.w};
    float4 mo, oo;
    float* mop = (float*)&mo;
    float* oop = (float*)&oo;
#pragma unroll
    for (int j = 0; j < 4; j++) {
        int cj = ch + j;
        float cur = (xs[j] - g_mean[cj]) * g_rstd[cj] * bnw[cj] + bnb[cj];
        float reset = (ms[j] > 1.0f) ? 1.0f : 0.0f;
        float mn    = 0.6f * ms[j] + cur - reset;
        mop[j] = mn;
        oop[j] = (mn > 1.0f) ? 1.0f : 0.0f;
    }
    ((float4*)g_mem[4])[i4] = mo;
    ((float4*)outp)[i4] = oo;
}

// ---------------------------------------------------------------------------
extern "C" void kernel_launch(void* const* d_in, const int* in_sizes, int n_in,
                              void* d_out, int out_size) {
    (void)in_sizes; (void)n_in; (void)out_size;
    const float* q   = (const float*)d_in[0];
    const float* k   = (const float*)d_in[1];
    const float* v   = (const float*)d_in[2];
    const float* qb  = (const float*)d_in[4];
    const float* kb  = (const float*)d_in[6];
    const float* vb  = (const float*)d_in[8];
    const float* pb  = (const float*)d_in[10];
    const float* bnw = (const float*)d_in[11];
    const float* bnb = (const float*)d_in[12];
    float* out = (float*)d_out;

    // One-time sync-primitive setup (first call is the eager correctness run,
    // outside graph capture). Initialization only; identical work every call.
    static cudaStream_t s2, s3;
    static cudaEvent_t  evCvt, evQ[4], evAt[4], evP[3];
    static bool inited = false;
    if (!inited) {
        cudaStreamCreateWithFlags(&s2, cudaStreamNonBlocking);
        cudaStreamCreateWithFlags(&s3, cudaStreamNonBlocking);
        cudaEventCreateWithFlags(&evCvt, cudaEventDisableTiming);
        for (int i = 0; i < 4; i++) cudaEventCreateWithFlags(&evQ[i], cudaEventDisableTiming);
        for (int i = 0; i < 4; i++) cudaEventCreateWithFlags(&evAt[i], cudaEventDisableTiming);
        for (int i = 0; i < 3; i++) cudaEventCreateWithFlags(&evP[i], cudaEventDisableTiming);
        cudaFuncSetAttribute(dense_mma_gemm, cudaFuncAttributeMaxDynamicSharedMemorySize,
                             DSM_BYTES);
        inited = true;
    }

    float* cq; cudaGetSymbolAddress((void**)&cq, g_cq);
    float* ck; cudaGetSymbolAddress((void**)&ck, g_ck);
    float* cv; cudaGetSymbolAddress((void**)&cv, g_cv);
    float* wc; cudaGetSymbolAddress((void**)&wc, g_wc);

    // Preamble (main stream)
    vout_copy_kernel<<<12288, 256>>>(v, out + (size_t)T_ * BCD);
    const int totalCvt = 3 * N4_IN + 4 * N4_W;
    cvt_all_kernel<<<(totalCvt + 255) / 256, 256>>>(
        (const float4*)q, (const float4*)k, (const float4*)v,
        (const float4*)d_in[3], (const float4*)d_in[5],
        (const float4*)d_in[7], (const float4*)d_in[9]);
    cudaEventRecord(evCvt, 0);

    auto launch_qkv = [&](int t) {
        const float* qt = cq + (size_t)t * BCD;
        const float* kt = ck + (size_t)t * BCD;
        const float* vt = cv + (size_t)t * BCD;
        dense_mma_gemm<<<dim3(12, 32, 3), 256, DSM_BYTES, s2>>>(
            qt, kt, vt, wc + 0 * D_ * D_, wc + 1 * D_ * D_, wc + 2 * D_ * D_,
            qb, kb, vb, 1, (t == 0) ? 1 : 0, t & 1);
        cudaEventRecord(evQ[t], s2);
    };

    cudaStreamWaitEvent(s2, evCvt, 0);
    launch_qkv(0);
    launch_qkv(1);

    for (int t = 0; t < T_; t++) {
        const int first = (t == 0) ? 1 : 0;
        const int bf = t & 1;

        // attn(t) on main: needs qkv(t); for t>=2 also needs proj(t-2) done
        // (spk3[bf] buffer release).
        cudaStreamWaitEvent(0, evQ[t], 0);
        if (t >= 2) cudaStreamWaitEvent(0, evP[t - 2], 0);
        attn_mma_kernel<<<dim3(4, 96), 256>>>(first, bf);
        cudaEventRecord(evAt[t], 0);

        // qkv(t+2) on s2 after attn(t) releases qb/kb/spk2[bf].
        if (t < 2) {
            cudaStreamWaitEvent(s2, evAt[t], 0);
            launch_qkv(t + 2);
        }

        if (t < 3) {
            // proj(t)+BN(t) on s3, overlapping attn(t+1) on main.
            cudaStreamWaitEvent(s3, evAt[t], 0);
            dense_mma_gemm<<<dim3(12, 32, 1), 256, DSM_BYTES, s3>>>(
                nullptr, nullptr, nullptr, wc + 3 * D_ * D_, nullptr, nullptr,
                pb, nullptr, nullptr, 0, 0, bf);
            bn_finalize_kernel<<<3, 256, 0, s3>>>();
            bn_apply_lif_kernel<<<3072, 256, 0, s3>>>(bnw, bnb,
                                                      out + (size_t)t * BCD, first);
            cudaEventRecord(evP[t], s3);
        } else {
            // Last step on main: join s3 back (evP[2] protects g_x2/g_bnsum/mem[4]).
            cudaStreamWaitEvent(0, evP[2], 0);
            dense_mma_gemm<<<dim3(12, 32, 1), 256, DSM_BYTES>>>(
                nullptr, nullptr, nullptr, wc + 3 * D_ * D_, nullptr, nullptr,
                pb, nullptr, nullptr, 0, 0, bf);
            bn_finalize_kernel<<<3, 256>>>();
            bn_apply_lif_kernel<<<3072, 256>>>(bnw, bnb, out + (size_t)t * BCD, first);
        }
    }
}